// round 4
// baseline (speedup 1.0000x reference)
#include <cuda_runtime.h>
#include <cuda_fp16.h>
#include <cstdint>

#define NN    50000
#define EE    250000
#define INF_  9
#define OUTF  84
#define CH    21            // float4 chunks per row (84/4)
#define EPS   1e-5f

#define FIN_BLOCKS  296
#define FIN_THREADS 336     // 16*21: chunk id constant per thread under grid stride
#define FIN_STRIDE  (FIN_BLOCKS * FIN_THREADS)   // 99456, divisible by 21
#define MAX_IT      11

#define PREP_NODES  64                  // nodes per block
#define PREP_PARS   4                   // chunk parities per node
#define PREP_THREADS (PREP_NODES * PREP_PARS)   // 256

// Scratch (static device globals; no runtime allocation)
__device__ __align__(16) uint4 g_uv[NN * CH];     // fp16 {u0..u3, v0..v3} per (node,chunk), row-major
__device__ __align__(16) float g_pre[NN * OUTF];  // x@root + bias, then += scatter-add(msg)
__device__ float g_stats[2 * OUTF];               // col sum, sumsq
__device__ float g_scale[OUTF];
__device__ float g_shift[OUTF];
__device__ int   g_count;
__device__ int   g_flag;
__device__ int   g_is64;

// ---------------------------------------------------------------------------
// Kernel A: weights staged in shared (warp-uniform broadcast LDS).
// Thread = (node, parity); each thread computes 5-6 chunks of u,v,pre.
__global__ void __launch_bounds__(PREP_THREADS)
prep_kernel(const float* __restrict__ x,
            const float* __restrict__ nn_w,
            const float* __restrict__ nn_b,
            const float* __restrict__ root,
            const float* __restrict__ bias,
            const int*   __restrict__ ei32) {
    __shared__ float4 swu[INF_ * CH];
    __shared__ float4 swv[INF_ * CH];
    __shared__ float4 swr[INF_ * CH];
    __shared__ float4 sbias[CH];

    const int tid = threadIdx.x;

    // One-time init (block 0): zero stats/sync, detect edge dtype.
    if (blockIdx.x == 0) {
        if (tid < 2 * OUTF) g_stats[tid] = 0.0f;
        if (tid == 0) {
            g_count = 0;
            g_flag = 0;
            int acc = 0;
            #pragma unroll
            for (int k = 0; k < 64; k++) acc |= ei32[2 * k + 1];  // int64 high dwords == 0
            g_is64 = (acc == 0) ? 1 : 0;
        }
    }

    // Cooperative weight staging: 189 float4 per matrix.
    const float4* w4 = (const float4*)nn_w;
    const float4* b4 = (const float4*)nn_b;
    const float4* r4 = (const float4*)root;
    for (int j = tid; j < INF_ * CH; j += PREP_THREADS) {
        swu[j] = w4[j];
        swv[j] = b4[j];
        swr[j] = r4[j];
    }
    if (tid < CH) sbias[tid] = ((const float4*)bias)[tid];
    __syncthreads();

    const int par     = tid / PREP_NODES;        // 0..3 (warp-uniform: 64 | 32)
    const int n_local = tid - par * PREP_NODES;
    const int n = blockIdx.x * PREP_NODES + n_local;
    if (n >= NN) return;

    float xr[INF_];
    #pragma unroll
    for (int i = 0; i < INF_; i++) xr[i] = x[n * INF_ + i];

    for (int c = par; c < CH; c += PREP_PARS) {
        float4 au = make_float4(0.f, 0.f, 0.f, 0.f);
        float4 av = make_float4(0.f, 0.f, 0.f, 0.f);
        float4 ap = sbias[c];
        #pragma unroll
        for (int i = 0; i < INF_; i++) {
            float4 wu = swu[i * CH + c];
            float4 wv = swv[i * CH + c];
            float4 wr = swr[i * CH + c];
            float xv = xr[i];
            au.x = fmaf(xv, wu.x, au.x); au.y = fmaf(xv, wu.y, au.y);
            au.z = fmaf(xv, wu.z, au.z); au.w = fmaf(xv, wu.w, au.w);
            av.x = fmaf(xv, wv.x, av.x); av.y = fmaf(xv, wv.y, av.y);
            av.z = fmaf(xv, wv.z, av.z); av.w = fmaf(xv, wv.w, av.w);
            ap.x = fmaf(xv, wr.x, ap.x); ap.y = fmaf(xv, wr.y, ap.y);
            ap.z = fmaf(xv, wr.z, ap.z); ap.w = fmaf(xv, wr.w, ap.w);
        }
        uint4 pk;
        *reinterpret_cast<__half2*>(&pk.x) = __floats2half2_rn(au.x, au.y);
        *reinterpret_cast<__half2*>(&pk.y) = __floats2half2_rn(au.z, au.w);
        *reinterpret_cast<__half2*>(&pk.z) = __floats2half2_rn(av.x, av.y);
        *reinterpret_cast<__half2*>(&pk.w) = __floats2half2_rn(av.z, av.w);
        g_uv[n * CH + c] = pk;
        *reinterpret_cast<float4*>(g_pre + n * OUTF + c * 4) = ap;
    }
}

// ---------------------------------------------------------------------------
// Kernel B: thread per (edge, chunk). msg4 = a*u4[src] + v4[src]; red.v4 into pre[dst].
// 21 consecutive threads share one edge -> index/attr loads broadcast, uv row
// gather reads 336B contiguous (full-line utilization).
__global__ void edge_kernel(const void* __restrict__ ei_raw,
                            const float* __restrict__ ea) {
    int t = blockIdx.x * blockDim.x + threadIdx.x;
    if (t >= EE * CH) return;
    int e = t / CH;
    int c = t - e * CH;

    int src, dst;
    if (g_is64) {
        const long long* ei = (const long long*)ei_raw;
        src = (int)ei[e];
        dst = (int)ei[EE + e];
    } else {
        const int* ei = (const int*)ei_raw;
        src = ei[e];
        dst = ei[EE + e];
    }
    float a = ea[e];

    uint4 pk = g_uv[src * CH + c];
    float2 u01 = __half22float2(*reinterpret_cast<__half2*>(&pk.x));
    float2 u23 = __half22float2(*reinterpret_cast<__half2*>(&pk.y));
    float2 v01 = __half22float2(*reinterpret_cast<__half2*>(&pk.z));
    float2 v23 = __half22float2(*reinterpret_cast<__half2*>(&pk.w));

    float4 m;
    m.x = fmaf(a, u01.x, v01.x);
    m.y = fmaf(a, u01.y, v01.y);
    m.z = fmaf(a, u23.x, v23.x);
    m.w = fmaf(a, u23.y, v23.y);

    float* dptr = g_pre + dst * OUTF + c * 4;
    asm volatile("red.global.add.v4.f32 [%0], {%1, %2, %3, %4};"
                 :: "l"(dptr), "f"(m.x), "f"(m.y), "f"(m.z), "f"(m.w)
                 : "memory");
}

// ---------------------------------------------------------------------------
// Kernel C: fused stats + batchnorm. 296 blocks x 336 threads, all co-resident.
__global__ void __launch_bounds__(FIN_THREADS, 2)
finish_kernel(const float* __restrict__ gamma,
              const float* __restrict__ beta,
              float4* __restrict__ out4) {
    const int tid = threadIdx.x;
    const int c = tid % CH;           // chunk constant per thread (stride % 21 == 0)
    const int col0 = c * 4;
    const float4* pre4 = (const float4*)g_pre;

    float4 vals[MAX_IT];
    float s[4] = {0.f, 0.f, 0.f, 0.f};
    float q[4] = {0.f, 0.f, 0.f, 0.f};
    int cnt = 0;
    for (int i = blockIdx.x * FIN_THREADS + tid; i < NN * CH; i += FIN_STRIDE) {
        float4 w = pre4[i];
        vals[cnt++] = w;
        s[0] += w.x; q[0] = fmaf(w.x, w.x, q[0]);
        s[1] += w.y; q[1] = fmaf(w.y, w.y, q[1]);
        s[2] += w.z; q[2] = fmaf(w.z, w.z, q[2]);
        s[3] += w.w; q[3] = fmaf(w.w, w.w, q[3]);
    }

    __shared__ float sh[8][FIN_THREADS];
    #pragma unroll
    for (int j = 0; j < 4; j++) { sh[j][tid] = s[j]; sh[4 + j][tid] = q[j]; }
    __syncthreads();
    if (tid < CH) {
        #pragma unroll
        for (int j = 0; j < 8; j++) {
            float acc = 0.f;
            #pragma unroll
            for (int r = 0; r < 16; r++) acc += sh[j][tid + r * CH];
            int col = tid * 4 + (j & 3);
            atomicAdd(&g_stats[(j < 4 ? 0 : OUTF) + col], acc);
        }
    }
    __syncthreads();

    __shared__ int sh_last;
    __threadfence();
    if (tid == 0) {
        int prev = atomicAdd(&g_count, 1);
        sh_last = (prev == FIN_BLOCKS - 1) ? 1 : 0;
    }
    __syncthreads();
    if (sh_last) {
        if (tid < OUTF) {
            const float invN = 1.0f / (float)NN;
            float mean = g_stats[tid] * invN;
            float var  = fmaf(-mean, mean, g_stats[OUTF + tid] * invN);
            float sc = rsqrtf(var + EPS) * gamma[tid];
            g_scale[tid] = sc;
            g_shift[tid] = fmaf(-mean, sc, beta[tid]);
        }
        __syncthreads();
        __threadfence();
        if (tid == 0) atomicExch(&g_flag, 1);
    }
    if (tid == 0) {
        volatile int* f = &g_flag;
        while (*f == 0) {}
    }
    __syncthreads();

    float sc[4], sf[4];
    #pragma unroll
    for (int j = 0; j < 4; j++) { sc[j] = g_scale[col0 + j]; sf[j] = g_shift[col0 + j]; }

    int k = 0;
    for (int i = blockIdx.x * FIN_THREADS + tid; i < NN * CH; i += FIN_STRIDE) {
        float4 w = vals[k++];
        w.x = fmaf(w.x, sc[0], sf[0]);
        w.y = fmaf(w.y, sc[1], sf[1]);
        w.z = fmaf(w.z, sc[2], sf[2]);
        w.w = fmaf(w.w, sc[3], sf[3]);
        out4[i] = w;
    }
}

// ---------------------------------------------------------------------------
extern "C" void kernel_launch(void* const* d_in, const int* in_sizes, int n_in,
                              void* d_out, int out_size) {
    const float* x     = (const float*)d_in[0];
    const void*  ei    = d_in[1];
    const float* ea    = (const float*)d_in[2];
    const float* nn_w  = (const float*)d_in[3];
    const float* nn_b  = (const float*)d_in[4];
    const float* root  = (const float*)d_in[5];
    const float* bias  = (const float*)d_in[6];
    const float* gamma = (const float*)d_in[7];
    const float* beta  = (const float*)d_in[8];
    float* out = (float*)d_out;

    {
        int blocks = (NN + PREP_NODES - 1) / PREP_NODES;   // 782
        prep_kernel<<<blocks, PREP_THREADS>>>(x, nn_w, nn_b, root, bias, (const int*)ei);
    }
    {
        int total = EE * CH;
        edge_kernel<<<(total + 255) / 256, 256>>>(ei, ea);
    }
    finish_kernel<<<FIN_BLOCKS, FIN_THREADS>>>(gamma, beta, (float4*)out);
}

// round 5
// speedup vs baseline: 1.0354x; 1.0354x over previous
#include <cuda_runtime.h>
#include <cuda_fp16.h>
#include <cstdint>

#define NN    50000
#define EE    250000
#define INF_  9
#define OUTF  84
#define CH    21            // float4 chunks per row (84/4)
#define EPS   1e-5f

#define FIN_BLOCKS  296
#define FIN_THREADS 336     // 16*21: chunk id constant per thread under grid stride
#define FIN_STRIDE  (FIN_BLOCKS * FIN_THREADS)   // 99456, divisible by 21
#define MAX_IT      11

#define PREP_NODES   48                 // nodes per block (smem budget)
#define PREP_PARS    4                  // chunk parities per node
#define PREP_THREADS (PREP_NODES * PREP_PARS)   // 192 = 6 warps

typedef unsigned long long ull;

// Scratch (static device globals; no runtime allocation)
__device__ __align__(16) uint4 g_uv[NN * CH];     // fp16 {u0..u3, v0..v3} per (node,chunk), row-major
__device__ __align__(16) float g_pre[NN * OUTF];  // x@root + bias, then += scatter-add(msg)
__device__ float g_stats[2 * OUTF];               // col sum, sumsq
__device__ float g_scale[OUTF];
__device__ float g_shift[OUTF];
__device__ int   g_count;
__device__ int   g_flag;
__device__ int   g_is64;

// ---- packed f32x2 helpers (FFMA2: PTX-only double-rate fp32) -------------
__device__ __forceinline__ ull pack2(float a, float b) {
    ull r; asm("mov.b64 %0, {%1, %2};" : "=l"(r) : "f"(a), "f"(b)); return r;
}
__device__ __forceinline__ float2 unpack2(ull v) {
    float2 r; asm("mov.b64 {%0, %1}, %2;" : "=f"(r.x), "=f"(r.y) : "l"(v)); return r;
}
__device__ __forceinline__ ull ffma2(ull a, ull b, ull c) {
    ull d; asm("fma.rn.f32x2 %0, %1, %2, %3;" : "=l"(d) : "l"(a), "l"(b), "l"(c)); return d;
}

// ---------------------------------------------------------------------------
// Kernel A: weights in shared (broadcast LDS), FFMA2 math, outputs staged in
// shared [c][n] then written out coalesced.
__global__ void __launch_bounds__(PREP_THREADS)
prep_kernel(const float* __restrict__ x,
            const float* __restrict__ nn_w,
            const float* __restrict__ nn_b,
            const float* __restrict__ root,
            const float* __restrict__ bias,
            const int*   __restrict__ ei32) {
    __shared__ float4 swu[INF_ * CH];
    __shared__ float4 swv[INF_ * CH];
    __shared__ float4 swr[INF_ * CH];
    __shared__ float4 sbias[CH];
    __shared__ uint4  s_uv [CH][PREP_NODES + 1];   // +1 pad: stagger banks for writeout
    __shared__ float4 s_pre[CH][PREP_NODES + 1];

    const int tid = threadIdx.x;

    // One-time init (block 0): zero stats/sync, detect edge dtype.
    if (blockIdx.x == 0) {
        if (tid < 2 * OUTF) g_stats[tid] = 0.0f;
        if (tid == 0) {
            g_count = 0;
            g_flag = 0;
            int acc = 0;
            #pragma unroll
            for (int k = 0; k < 64; k++) acc |= ei32[2 * k + 1];  // int64 high dwords == 0
            g_is64 = (acc == 0) ? 1 : 0;
        }
    }

    // Cooperative weight staging: 189 float4 per matrix.
    const float4* w4 = (const float4*)nn_w;
    const float4* b4 = (const float4*)nn_b;
    const float4* r4 = (const float4*)root;
    for (int j = tid; j < INF_ * CH; j += PREP_THREADS) {
        swu[j] = w4[j];
        swv[j] = b4[j];
        swr[j] = r4[j];
    }
    if (tid < CH) sbias[tid] = ((const float4*)bias)[tid];
    __syncthreads();

    const int par     = tid / PREP_NODES;        // 0..3
    const int n_local = tid - par * PREP_NODES;  // 0..47
    const int n0 = blockIdx.x * PREP_NODES;
    const int n  = n0 + n_local;

    if (n < NN) {
        ull xp[INF_];
        #pragma unroll
        for (int i = 0; i < INF_; i++) {
            float xv = x[n * INF_ + i];
            xp[i] = pack2(xv, xv);
        }

        const ulonglong2* wu2 = (const ulonglong2*)swu;
        const ulonglong2* wv2 = (const ulonglong2*)swv;
        const ulonglong2* wr2 = (const ulonglong2*)swr;

        for (int c = par; c < CH; c += PREP_PARS) {
            ull au01 = 0ull, au23 = 0ull, av01 = 0ull, av23 = 0ull;
            float4 bv = sbias[c];
            ull ap01 = pack2(bv.x, bv.y);
            ull ap23 = pack2(bv.z, bv.w);
            #pragma unroll
            for (int i = 0; i < INF_; i++) {
                ulonglong2 wu = wu2[i * CH + c];
                ulonglong2 wv = wv2[i * CH + c];
                ulonglong2 wr = wr2[i * CH + c];
                ull xv = xp[i];
                au01 = ffma2(xv, wu.x, au01); au23 = ffma2(xv, wu.y, au23);
                av01 = ffma2(xv, wv.x, av01); av23 = ffma2(xv, wv.y, av23);
                ap01 = ffma2(xv, wr.x, ap01); ap23 = ffma2(xv, wr.y, ap23);
            }
            float2 u01 = unpack2(au01), u23 = unpack2(au23);
            float2 v01 = unpack2(av01), v23 = unpack2(av23);
            uint4 pk;
            *reinterpret_cast<__half2*>(&pk.x) = __floats2half2_rn(u01.x, u01.y);
            *reinterpret_cast<__half2*>(&pk.y) = __floats2half2_rn(u23.x, u23.y);
            *reinterpret_cast<__half2*>(&pk.z) = __floats2half2_rn(v01.x, v01.y);
            *reinterpret_cast<__half2*>(&pk.w) = __floats2half2_rn(v23.x, v23.y);
            s_uv[c][n_local] = pk;
            float2 p01 = unpack2(ap01), p23 = unpack2(ap23);
            s_pre[c][n_local] = make_float4(p01.x, p01.y, p23.x, p23.y);
        }
    }
    __syncthreads();

    // Coalesced writeout: linear j = n*CH + c within the block tile.
    const int nb = min(PREP_NODES, NN - n0);
    const int base = n0 * CH;
    uint4*  guv4  = g_uv;
    float4* gpre4 = (float4*)g_pre;
    for (int j = tid; j < nb * CH; j += PREP_THREADS) {
        int nn_ = j / CH;
        int c   = j - nn_ * CH;
        guv4 [base + j] = s_uv [c][nn_];
        gpre4[base + j] = s_pre[c][nn_];
    }
}

// ---------------------------------------------------------------------------
// Kernel B: thread per (edge, chunk). msg4 = a*u4[src] + v4[src]; red.v4 into pre[dst].
__global__ void edge_kernel(const void* __restrict__ ei_raw,
                            const float* __restrict__ ea) {
    int t = blockIdx.x * blockDim.x + threadIdx.x;
    if (t >= EE * CH) return;
    int e = t / CH;
    int c = t - e * CH;

    int src, dst;
    if (g_is64) {
        const long long* ei = (const long long*)ei_raw;
        src = (int)ei[e];
        dst = (int)ei[EE + e];
    } else {
        const int* ei = (const int*)ei_raw;
        src = ei[e];
        dst = ei[EE + e];
    }
    float a = ea[e];

    uint4 pk = g_uv[src * CH + c];
    float2 u01 = __half22float2(*reinterpret_cast<__half2*>(&pk.x));
    float2 u23 = __half22float2(*reinterpret_cast<__half2*>(&pk.y));
    float2 v01 = __half22float2(*reinterpret_cast<__half2*>(&pk.z));
    float2 v23 = __half22float2(*reinterpret_cast<__half2*>(&pk.w));

    float4 m;
    m.x = fmaf(a, u01.x, v01.x);
    m.y = fmaf(a, u01.y, v01.y);
    m.z = fmaf(a, u23.x, v23.x);
    m.w = fmaf(a, u23.y, v23.y);

    float* dptr = g_pre + dst * OUTF + c * 4;
    asm volatile("red.global.add.v4.f32 [%0], {%1, %2, %3, %4};"
                 :: "l"(dptr), "f"(m.x), "f"(m.y), "f"(m.z), "f"(m.w)
                 : "memory");
}

// ---------------------------------------------------------------------------
// Kernel C: fused stats + batchnorm. 296 blocks x 336 threads, all co-resident.
__global__ void __launch_bounds__(FIN_THREADS, 2)
finish_kernel(const float* __restrict__ gamma,
              const float* __restrict__ beta,
              float4* __restrict__ out4) {
    const int tid = threadIdx.x;
    const int c = tid % CH;           // chunk constant per thread (stride % 21 == 0)
    const int col0 = c * 4;
    const float4* pre4 = (const float4*)g_pre;

    float4 vals[MAX_IT];
    float s[4] = {0.f, 0.f, 0.f, 0.f};
    float q[4] = {0.f, 0.f, 0.f, 0.f};
    int cnt = 0;
    for (int i = blockIdx.x * FIN_THREADS + tid; i < NN * CH; i += FIN_STRIDE) {
        float4 w = pre4[i];
        vals[cnt++] = w;
        s[0] += w.x; q[0] = fmaf(w.x, w.x, q[0]);
        s[1] += w.y; q[1] = fmaf(w.y, w.y, q[1]);
        s[2] += w.z; q[2] = fmaf(w.z, w.z, q[2]);
        s[3] += w.w; q[3] = fmaf(w.w, w.w, q[3]);
    }

    __shared__ float sh[8][FIN_THREADS];
    #pragma unroll
    for (int j = 0; j < 4; j++) { sh[j][tid] = s[j]; sh[4 + j][tid] = q[j]; }
    __syncthreads();
    if (tid < CH) {
        #pragma unroll
        for (int j = 0; j < 8; j++) {
            float acc = 0.f;
            #pragma unroll
            for (int r = 0; r < 16; r++) acc += sh[j][tid + r * CH];
            int col = tid * 4 + (j & 3);
            atomicAdd(&g_stats[(j < 4 ? 0 : OUTF) + col], acc);
        }
    }
    __syncthreads();

    __shared__ int sh_last;
    __threadfence();
    if (tid == 0) {
        int prev = atomicAdd(&g_count, 1);
        sh_last = (prev == FIN_BLOCKS - 1) ? 1 : 0;
    }
    __syncthreads();
    if (sh_last) {
        if (tid < OUTF) {
            const float invN = 1.0f / (float)NN;
            float mean = g_stats[tid] * invN;
            float var  = fmaf(-mean, mean, g_stats[OUTF + tid] * invN);
            float sc = rsqrtf(var + EPS) * gamma[tid];
            g_scale[tid] = sc;
            g_shift[tid] = fmaf(-mean, sc, beta[tid]);
        }
        __syncthreads();
        __threadfence();
        if (tid == 0) atomicExch(&g_flag, 1);
    }
    if (tid == 0) {
        volatile int* f = &g_flag;
        while (*f == 0) {}
    }
    __syncthreads();

    float sc[4], sf[4];
    #pragma unroll
    for (int j = 0; j < 4; j++) { sc[j] = g_scale[col0 + j]; sf[j] = g_shift[col0 + j]; }

    int k = 0;
    for (int i = blockIdx.x * FIN_THREADS + tid; i < NN * CH; i += FIN_STRIDE) {
        float4 w = vals[k++];
        w.x = fmaf(w.x, sc[0], sf[0]);
        w.y = fmaf(w.y, sc[1], sf[1]);
        w.z = fmaf(w.z, sc[2], sf[2]);
        w.w = fmaf(w.w, sc[3], sf[3]);
        out4[i] = w;
    }
}

// ---------------------------------------------------------------------------
extern "C" void kernel_launch(void* const* d_in, const int* in_sizes, int n_in,
                              void* d_out, int out_size) {
    const float* x     = (const float*)d_in[0];
    const void*  ei    = d_in[1];
    const float* ea    = (const float*)d_in[2];
    const float* nn_w  = (const float*)d_in[3];
    const float* nn_b  = (const float*)d_in[4];
    const float* root  = (const float*)d_in[5];
    const float* bias  = (const float*)d_in[6];
    const float* gamma = (const float*)d_in[7];
    const float* beta  = (const float*)d_in[8];
    float* out = (float*)d_out;

    {
        int blocks = (NN + PREP_NODES - 1) / PREP_NODES;   // 1042
        prep_kernel<<<blocks, PREP_THREADS>>>(x, nn_w, nn_b, root, bias, (const int*)ei);
    }
    {
        int total = EE * CH;
        edge_kernel<<<(total + 255) / 256, 256>>>(ei, ea);
    }
    finish_kernel<<<FIN_BLOCKS, FIN_THREADS>>>(gamma, beta, (float4*)out);
}